// round 9
// baseline (speedup 1.0000x reference)
#include <cuda_runtime.h>
#include <cuda_bf16.h>

// Problem constants
#define BATCH   32768
#define D       768          // 3*16*16 compressed features per sample
#define D4      192          // D/4

__device__ float g_weff[D];

// ---------------------------------------------------------------------------
// Kernel 1: fold lhs/rhs/W into W_eff[768]. One block per output element.
// ---------------------------------------------------------------------------
__global__ void fold_weff_kernel(const float* __restrict__ lhs,   // [2,16,8]
                                 const float* __restrict__ rhs,   // [2,8,16]
                                 const float* __restrict__ W)     // [3072]
{
    const int o   = blockIdx.x;          // 0..767
    const int ch  = o >> 8;
    const int rem = o & 255;
    const int rr  = rem >> 4;
    const int cc  = rem & 15;
    const int r   = rr >> 3;
    const int p   = rr & 7;
    const int c   = cc >> 3;
    const int q   = cc & 7;

    const int t = threadIdx.x;           // 0..255
    const int P = t >> 4;
    const int Q = t & 15;

    float term = lhs[r * 128 + P * 8 + p]
               * rhs[c * 128 + q * 16 + Q]
               * W[ch * 1024 + (r * 16 + P) * 32 + (c * 16 + Q)];

    #pragma unroll
    for (int off = 16; off > 0; off >>= 1)
        term += __shfl_xor_sync(0xFFFFFFFFu, term, off);

    __shared__ float warp_sums[8];
    const int lane = t & 31;
    const int wid  = t >> 5;
    if (lane == 0) warp_sums[wid] = term;
    __syncthreads();

    if (t == 0) {
        float s = 0.f;
        #pragma unroll
        for (int w = 0; w < 8; w++) s += warp_sums[w];
        g_weff[o] = s;
    }
#if __CUDA_ARCH__ >= 900
    cudaTriggerProgrammaticLaunchCompletion();
#endif
}

// x load: ld.global.cg.v4 via volatile asm — guaranteed issue order/placement,
// L2-cached with NORMAL evict priority (keeps x resident across graph replays).
#define LDGCG4(dst, addr)                                                     \
    asm volatile("ld.global.cg.v4.f32 {%0,%1,%2,%3}, [%4];"                   \
                 : "=f"(dst.x), "=f"(dst.y), "=f"(dst.z), "=f"(dst.w)         \
                 : "l"(addr))

// ---------------------------------------------------------------------------
// Kernel 2 (PDL secondary): out[n] = dot(x[n,:], W_eff) + b.
// 8 warps x 2 rows = 16 rows/block. All 12 x loads are volatile-asm
// front-batched BEFORE the grid dependency sync -> MLP=12/warp guaranteed.
// ---------------------------------------------------------------------------
__global__ __launch_bounds__(256)
void gemv_pdl_kernel(const float4* __restrict__ x,    // [BATCH * D4]
                     const float*  __restrict__ bptr, // [1]
                     float*        __restrict__ out)  // [BATCH]
{
    const int t    = threadIdx.x;
    const int warp = t >> 5;
    const int lane = t & 31;
    const int row0 = (blockIdx.x * 8 + warp) * 2;

    const float4* xr0 = x + (size_t)row0 * D4 + lane;
    const float4* xr1 = xr0 + D4;

    // 12 consecutive LDG.E.CG.128 — ptxas cannot reorder volatile asm.
    float4 v0a, v0b, v0c, v0d, v0e, v0f;
    float4 v1a, v1b, v1c, v1d, v1e, v1f;
    LDGCG4(v0a, xr0 +   0); LDGCG4(v0b, xr0 +  32); LDGCG4(v0c, xr0 +  64);
    LDGCG4(v0d, xr0 +  96); LDGCG4(v0e, xr0 + 128); LDGCG4(v0f, xr0 + 160);
    LDGCG4(v1a, xr1 +   0); LDGCG4(v1b, xr1 +  32); LDGCG4(v1c, xr1 +  64);
    LDGCG4(v1d, xr1 +  96); LDGCG4(v1e, xr1 + 128); LDGCG4(v1f, xr1 + 160);

#if __CUDA_ARCH__ >= 900
    cudaGridDependencySynchronize();     // fold's g_weff now visible
#endif

    const float4* __restrict__ w4 = reinterpret_cast<const float4*>(g_weff);

    float a0 = 0.f, a1 = 0.f;
    float4 w;
    #define ACC(k, V0, V1)                                                    \
        w = __ldg(&w4[lane + (k) * 32]);                                      \
        a0 = fmaf(V0.x, w.x, a0); a0 = fmaf(V0.y, w.y, a0);                   \
        a0 = fmaf(V0.z, w.z, a0); a0 = fmaf(V0.w, w.w, a0);                   \
        a1 = fmaf(V1.x, w.x, a1); a1 = fmaf(V1.y, w.y, a1);                   \
        a1 = fmaf(V1.z, w.z, a1); a1 = fmaf(V1.w, w.w, a1);
    ACC(0, v0a, v1a) ACC(1, v0b, v1b) ACC(2, v0c, v1c)
    ACC(3, v0d, v1d) ACC(4, v0e, v1e) ACC(5, v0f, v1f)
    #undef ACC

    #pragma unroll
    for (int off = 16; off > 0; off >>= 1) {
        a0 += __shfl_xor_sync(0xFFFFFFFFu, a0, off);
        a1 += __shfl_xor_sync(0xFFFFFFFFu, a1, off);
    }

    if (lane == 0) {
        const float bb = bptr[0];
        out[row0]     = a0 + bb;
        out[row0 + 1] = a1 + bb;
    }
}

// ---------------------------------------------------------------------------
extern "C" void kernel_launch(void* const* d_in, const int* in_sizes, int n_in,
                              void* d_out, int out_size)
{
    const float* x   = (const float*)d_in[0];   // [32768, 3, 16, 16]
    const float* lhs = (const float*)d_in[1];   // [2, 16, 8]
    const float* rhs = (const float*)d_in[2];   // [2, 8, 16]
    const float* W   = (const float*)d_in[3];   // [1, 3072]
    const float* b   = (const float*)d_in[4];   // [1]
    float* out       = (float*)d_out;           // [32768]

    // Primary: fold kernel (768 blocks x 256 threads)
    fold_weff_kernel<<<D, 256>>>(lhs, rhs, W);

    // Secondary: gemv with programmatic dependent launch (overlaps fold tail)
    cudaLaunchConfig_t cfg = {};
    cfg.gridDim  = dim3(BATCH / 16);   // 2048
    cfg.blockDim = dim3(256);
    cfg.dynamicSmemBytes = 0;
    cfg.stream = 0;

    cudaLaunchAttribute attrs[1];
    attrs[0].id = cudaLaunchAttributeProgrammaticStreamSerialization;
    attrs[0].val.programmaticStreamSerializationAllowed = 1;
    cfg.attrs    = attrs;
    cfg.numAttrs = 1;

    cudaLaunchKernelEx(&cfg, gemv_pdl_kernel,
                       (const float4*)x, (const float*)b, (float*)out);
}